// round 6
// baseline (speedup 1.0000x reference)
#include <cuda_runtime.h>
#include <stdint.h>

// TestSpatialTransform == two center crops of (4,2,192,192,192) -> (4,2,160,160,160).
// Pure HBM copy at minimum traffic (524 MB). Measured ceiling ~6.6 TB/s.
// This round: MLP=4 with INTRA-THREAD CONTIGUITY — each thread moves two
// adjacent float4 (32 B contiguous) from data and the same 32 B from seg:
// per-thread loads pair up in the same DRAM row (row-buffer hits), warp
// footprint 1 KB contiguous per tensor. Writes fully coalesced.

#define PATCH 160
#define SRC   192
#define OFF   16
#define W8    (PATCH / 8)                          // 20 float4-pairs per row
#define N_PAIR (8 * PATCH * PATCH * W8)            // 4,096,000 pairs per tensor
#define N_F4_PER_TENSOR (8 * PATCH * PATCH * (PATCH / 4))   // 8,192,000

__global__ void __launch_bounds__(256)
crop_copy_pair_kernel(const float* __restrict__ data,
                      const float* __restrict__ seg,
                      float4* __restrict__ out)
{
    int idx = blockIdx.x * blockDim.x + threadIdx.x;   // 0 .. N_PAIR-1 exact

    int w8 = idx % W8;
    int t  = idx / W8;
    int h  = t % PATCH; t /= PATCH;
    int d  = t % PATCH;
    int bc = t / PATCH;

    // source flat float index within (8, 192, 192, 192); 8 floats per pair
    int sidx = (((bc * SRC) + (d + OFF)) * SRC + (h + OFF)) * SRC + OFF + (w8 << 3);

    const float4* sd = reinterpret_cast<const float4*>(data + sidx);
    const float4* ss = reinterpret_cast<const float4*>(seg  + sidx);

    // four independent loads; two contiguous per tensor (same DRAM row)
    float4 a0 = __ldcs(sd);
    float4 a1 = __ldcs(sd + 1);
    float4 b0 = __ldcs(ss);
    float4 b1 = __ldcs(ss + 1);

    // dest float4 index: each pair = 2 consecutive float4
    int didx = idx << 1;
    __stcs(out + didx,     a0);
    __stcs(out + didx + 1, a1);
    __stcs(out + didx + N_F4_PER_TENSOR,     b0);
    __stcs(out + didx + N_F4_PER_TENSOR + 1, b1);
}

extern "C" void kernel_launch(void* const* d_in, const int* in_sizes, int n_in,
                              void* d_out, int out_size)
{
    const float* data = (const float*)d_in[0];
    const float* seg  = (const float*)d_in[1];
    float4* out = (float4*)d_out;

    const int threads = 256;
    const int blocks  = N_PAIR / threads;   // 16000 exactly, no tail
    crop_copy_pair_kernel<<<blocks, threads>>>(data, seg, out);
}